// round 3
// baseline (speedup 1.0000x reference)
#include <cuda_runtime.h>
#include <math.h>
#include <stdint.h>

#define T_LEN 2048
#define B_SZ  2
#define EMB   768
#define NH    12
#define HD    64
#define MROWS 4096

// ---------------- scratch (device globals) ---------------------------------
__device__ float g_q[MROWS * EMB];
__device__ float g_k[MROWS * EMB];
__device__ float g_v[MROWS * EMB];
__device__ float g_att[MROWS * EMB];
__device__ float g_bias[NH * 4096];   // [h][rel + 2048], rel = s - t

// ---------------- helpers ---------------------------------------------------
__device__ __forceinline__ uint32_t smu32(const void* p) {
    uint32_t a;
    asm("{.reg .u64 t; cvta.to.shared.u64 t, %1; cvt.u32.u64 %0, t;}"
        : "=r"(a) : "l"(p));
    return a;
}
__device__ __forceinline__ void cp16(uint32_t d, const void* s) {
    asm volatile("cp.async.cg.shared.global [%0], [%1], 16;" :: "r"(d), "l"(s));
}
__device__ __forceinline__ void cp_commit() {
    asm volatile("cp.async.commit_group;");
}
template <int N> __device__ __forceinline__ void cp_wait() {
    asm volatile("cp.async.wait_group %0;" :: "n"(N));
}
__device__ __forceinline__ uint32_t tfu(float x) {
    uint32_t r;
    asm("cvt.rna.tf32.f32 %0, %1;" : "=r"(r) : "f"(x));
    return r;
}
__device__ __forceinline__ float tff(float x) { return __uint_as_float(tfu(x)); }

__device__ __forceinline__ void mma_tf32(float c[4], const uint32_t a[4],
                                         const uint32_t b[2]) {
    asm volatile(
        "mma.sync.aligned.m16n8k8.row.col.f32.tf32.tf32.f32 "
        "{%0,%1,%2,%3},{%4,%5,%6,%7},{%8,%9},{%0,%1,%2,%3};"
        : "+f"(c[0]), "+f"(c[1]), "+f"(c[2]), "+f"(c[3])
        : "r"(a[0]), "r"(a[1]), "r"(a[2]), "r"(a[3]), "r"(b[0]), "r"(b[1]));
}

// ---------------- T5 relative bias LUT ------------------------------------
__global__ void bias_lut_kernel(const float* __restrict__ rel_bias) {
    int idx = blockIdx.x * blockDim.x + threadIdx.x;
    if (idx >= NH * 4096) return;
    int h   = idx >> 12;
    int rel = (idx & 4095) - 2048;
    int bucket = (rel > 0) ? 16 : 0;
    int rp = rel < 0 ? -rel : rel;
    if (rp < 8) {
        bucket += rp;
    } else {
        float lf = logf((float)rp / 8.0f) / 2.7725887298583984f * 8.0f;
        int large = 8 + (int)lf;
        bucket += (large < 15) ? large : 15;
    }
    g_bias[idx] = rel_bias[bucket * NH + h];
}

// ---------------- tf32 SGEMM, 3-stage cp.async pipeline --------------------
struct GArgs {
    const float* X[3]; const float* W[3]; const float* Bv[3];
    float* Y[3]; float scale[3];
};

#define AST 20     // A smem stride (≡4 mod 32; rows 16B-aligned: 80B)
#define BST 136    // B smem stride (≡8 mod 32; rows 544B)
#define SGA (128 * AST)     // 2560 floats
#define SGB (16 * BST)      // 2176 floats
#define SGS (SGA + SGB)     // 4736 floats/stage; 3 stages = 56832 B

__global__ __launch_bounds__(256, 2)
void sgemm_tf32_v2(GArgs args) {
    extern __shared__ float sm[];
    int z = blockIdx.z;
    const float* X = args.X[z];
    const float* W = args.W[z];
    const float* bias = args.Bv[z];
    float* Y = args.Y[z];
    float scale = args.scale[z];

    int tid = threadIdx.x, lane = tid & 31, w = tid >> 5;
    int wm = w & 3, wn = w >> 2, lr = lane >> 2, lc = lane & 3;
    int m0 = blockIdx.y << 7, n0 = blockIdx.x << 7;
    uint32_t sbase = smu32(sm);

    auto issue = [&](int kt, int slot) {
        int k0 = kt * 16;
        uint32_t abase = sbase + slot * SGS * 4;
        uint32_t bbase = abase + SGA * 4;
#pragma unroll
        for (int i = 0; i < 2; i++) {
            int e = tid + i * 256;
            int row = e >> 2, c4 = (e & 3) << 2;
            cp16(abase + (row * AST + c4) * 4, &X[(m0 + row) * EMB + k0 + c4]);
        }
#pragma unroll
        for (int i = 0; i < 2; i++) {
            int e = tid + i * 256;
            int k = e >> 5, nc = (e & 31) << 2;
            cp16(bbase + (k * BST + nc) * 4, &W[(k0 + k) * EMB + n0 + nc]);
        }
    };

    float acc[2][8][4];
#pragma unroll
    for (int mt = 0; mt < 2; mt++)
#pragma unroll
        for (int nt = 0; nt < 8; nt++)
#pragma unroll
            for (int i = 0; i < 4; i++) acc[mt][nt][i] = 0.f;

    issue(0, 0); cp_commit();
    issue(1, 1); cp_commit();

    for (int kt = 0; kt < 48; kt++) {
        __syncthreads();                 // slot (kt+2)%3 free across all warps
        if (kt + 2 < 48) issue(kt + 2, (kt + 2) % 3);
        cp_commit();                     // empty group when out of tiles
        cp_wait<2>();                    // stage kt landed
        __syncthreads();

        const float* sa = sm + (kt % 3) * SGS;
        const float* sb = sa + SGA;
#pragma unroll
        for (int ks = 0; ks < 2; ks++) {
            int kk = ks * 8;
            uint32_t a[2][4], bf[8][2];
#pragma unroll
            for (int mt = 0; mt < 2; mt++) {
                int base = wm * 32 + mt * 16;
                a[mt][0] = tfu(sa[(base + lr)     * AST + kk + lc]);
                a[mt][1] = tfu(sa[(base + lr + 8) * AST + kk + lc]);
                a[mt][2] = tfu(sa[(base + lr)     * AST + kk + lc + 4]);
                a[mt][3] = tfu(sa[(base + lr + 8) * AST + kk + lc + 4]);
            }
#pragma unroll
            for (int nt = 0; nt < 8; nt++) {
                int nb = wn * 64 + nt * 8 + lr;
                bf[nt][0] = tfu(sb[(kk + lc)     * BST + nb]);
                bf[nt][1] = tfu(sb[(kk + lc + 4) * BST + nb]);
            }
#pragma unroll
            for (int mt = 0; mt < 2; mt++)
#pragma unroll
                for (int nt = 0; nt < 8; nt++)
                    mma_tf32(acc[mt][nt], a[mt], bf[nt]);
        }
    }

#pragma unroll
    for (int mt = 0; mt < 2; mt++) {
        int row = m0 + wm * 32 + mt * 16 + lr;
#pragma unroll
        for (int nt = 0; nt < 8; nt++) {
            int col = n0 + wn * 64 + nt * 8 + 2 * lc;
            float b0 = bias[col], b1 = bias[col + 1];
            *(float2*)&Y[row * EMB + col] =
                make_float2((acc[mt][nt][0] + b0) * scale,
                            (acc[mt][nt][1] + b1) * scale);
            *(float2*)&Y[(row + 8) * EMB + col] =
                make_float2((acc[mt][nt][2] + b0) * scale,
                            (acc[mt][nt][3] + b1) * scale);
        }
    }
}

// ---------------- tf32 flash attention, double-buffered K/V ----------------
// 128 q-rows/CTA, S-tiles of 32, 8 warps (one m16 band each).
#define QST 68
#define KST 68
#define VST 72
#define PST 36
#define SMQ 0
#define SMK 8704
#define KSTG 2176          // floats per K stage
#define SMV 13056
#define VSTG 2304          // floats per V stage
#define SMP 17664
#define SMB 22272          // bias slice: 2175 floats
#define SMM 24448          // mask bytes: 2048 B (512 floats)
#define SMTOT 24960        // floats -> 99840 B

__global__ __launch_bounds__(256, 2)
void attn_tf32_v2(const unsigned char* __restrict__ maskg) {
    extern __shared__ float sm[];
    int tid = threadIdx.x, lane = tid & 31, w = tid >> 5;
    int lr = lane >> 2, lc = lane & 3;
    int bh = blockIdx.y;
    int b = bh / NH, h = bh % NH;
    int t0 = blockIdx.x * 128;
    uint32_t sbase = smu32(sm);
    unsigned char* smask = (unsigned char*)(sm + SMM);
    int tr0l = w * 16 + lr, tr1l = tr0l + 8;

    auto issue_kv = [&](int kt2, int slot) {
        int s0 = kt2 * 32;
        uint32_t kb = sbase + (SMK + slot * KSTG) * 4;
        uint32_t vb = sbase + (SMV + slot * VSTG) * 4;
#pragma unroll
        for (int i = 0; i < 2; i++) {
            int e = tid + i * 256;
            int row = e >> 4, c4 = (e & 15) << 2;
            cp16(kb + (row * KST + c4) * 4,
                 &g_k[((s0 + row) * B_SZ + b) * EMB + h * HD + c4]);
        }
#pragma unroll
        for (int i = 0; i < 2; i++) {
            int e = tid + i * 256;
            int row = e >> 4, c4 = (e & 15) << 2;
            cp16(vb + (row * VST + c4) * 4,
                 &g_v[((s0 + row) * B_SZ + b) * EMB + h * HD + c4]);
        }
    };

    // Q (tf32), bias slice, mask row: all staged once
#pragma unroll
    for (int i = 0; i < 8; i++) {
        int e = tid + i * 256;
        int row = e >> 4, c4 = (e & 15) << 2;
        float4 v = *(const float4*)&g_q[((t0 + row) * B_SZ + b) * EMB + h * HD + c4];
        float* d = &sm[SMQ + row * QST + c4];
        d[0] = tff(v.x); d[1] = tff(v.y); d[2] = tff(v.z); d[3] = tff(v.w);
    }
    for (int i = tid; i < 2175; i += 256)
        sm[SMB + i] = g_bias[h * 4096 + i + 1921 - t0];
    if (tid < 128)
        ((float4*)smask)[tid] = ((const float4*)(maskg + b * T_LEN))[tid];

    issue_kv(0, 0); cp_commit();

    float o[8][4];
#pragma unroll
    for (int nt = 0; nt < 8; nt++)
#pragma unroll
        for (int i = 0; i < 4; i++) o[nt][i] = 0.f;
    float m0s = -1e30f, m1s = -1e30f, l0s = 0.f, l1s = 0.f;

    for (int kt = 0; kt < 64; kt++) {
        __syncthreads();                       // prev compute done everywhere
        if (kt + 1 < 64) issue_kv(kt + 1, (kt + 1) & 1);
        cp_commit();
        cp_wait<1>();                          // stage kt landed
        __syncthreads();

        int slot = kt & 1;
        float* Ks = sm + SMK + slot * KSTG;
        float* Vs = sm + SMV + slot * VSTG;

        // in-place fp32 -> tf32 pass (once per element, shared by all warps)
#pragma unroll
        for (int i = 0; i < 2; i++) {
            int e = tid + i * 256;
            float4* p = (float4*)&Ks[(e >> 4) * KST + ((e & 15) << 2)];
            float4 v = *p;
            v.x = tff(v.x); v.y = tff(v.y); v.z = tff(v.z); v.w = tff(v.w);
            *p = v;
        }
#pragma unroll
        for (int i = 0; i < 2; i++) {
            int e = tid + i * 256;
            float4* p = (float4*)&Vs[(e >> 4) * VST + ((e & 15) << 2)];
            float4 v = *p;
            v.x = tff(v.x); v.y = tff(v.y); v.z = tff(v.z); v.w = tff(v.w);
            *p = v;
        }
        __syncthreads();

        int s0 = kt * 32;

        // S = Q K^T  (m16 x n32 x k64)
        float s4[4][4];
#pragma unroll
        for (int nt = 0; nt < 4; nt++)
#pragma unroll
            for (int i = 0; i < 4; i++) s4[nt][i] = 0.f;
#pragma unroll
        for (int ks = 0; ks < 8; ks++) {
            int kk = ks * 8;
            uint32_t a[4], bf[4][2];
            a[0] = __float_as_uint(sm[SMQ + tr0l * QST + kk + lc]);
            a[1] = __float_as_uint(sm[SMQ + tr1l * QST + kk + lc]);
            a[2] = __float_as_uint(sm[SMQ + tr0l * QST + kk + lc + 4]);
            a[3] = __float_as_uint(sm[SMQ + tr1l * QST + kk + lc + 4]);
#pragma unroll
            for (int nt = 0; nt < 4; nt++) {
                int nb = nt * 8 + lr;
                bf[nt][0] = __float_as_uint(Ks[nb * KST + kk + lc]);
                bf[nt][1] = __float_as_uint(Ks[nb * KST + kk + lc + 4]);
            }
#pragma unroll
            for (int nt = 0; nt < 4; nt++) mma_tf32(s4[nt], a, bf[nt]);
        }

        // bias + mask (all smem-resident)
#pragma unroll
        for (int nt = 0; nt < 4; nt++) {
            int c0 = nt * 8 + 2 * lc, c1 = c0 + 1;
            float mk0 = smask[s0 + c0] ? -1e30f : 0.f;
            float mk1 = smask[s0 + c1] ? -1e30f : 0.f;
            s4[nt][0] += sm[SMB + s0 + c0 - tr0l + 127] + mk0;
            s4[nt][1] += sm[SMB + s0 + c1 - tr0l + 127] + mk1;
            s4[nt][2] += sm[SMB + s0 + c0 - tr1l + 127] + mk0;
            s4[nt][3] += sm[SMB + s0 + c1 - tr1l + 127] + mk1;
        }

        // online softmax over 32 cols
        float r0 = -1e30f, r1 = -1e30f;
#pragma unroll
        for (int nt = 0; nt < 4; nt++) {
            r0 = fmaxf(r0, fmaxf(s4[nt][0], s4[nt][1]));
            r1 = fmaxf(r1, fmaxf(s4[nt][2], s4[nt][3]));
        }
        r0 = fmaxf(r0, __shfl_xor_sync(0xffffffffu, r0, 1));
        r0 = fmaxf(r0, __shfl_xor_sync(0xffffffffu, r0, 2));
        r1 = fmaxf(r1, __shfl_xor_sync(0xffffffffu, r1, 1));
        r1 = fmaxf(r1, __shfl_xor_sync(0xffffffffu, r1, 2));
        float mn0 = fmaxf(m0s, r0), mn1 = fmaxf(m1s, r1);
        float cr0 = __expf(m0s - mn0), cr1 = __expf(m1s - mn1);
        float ls0 = 0.f, ls1 = 0.f;
#pragma unroll
        for (int nt = 0; nt < 4; nt++) {
            s4[nt][0] = __expf(s4[nt][0] - mn0); ls0 += s4[nt][0];
            s4[nt][1] = __expf(s4[nt][1] - mn0); ls0 += s4[nt][1];
            s4[nt][2] = __expf(s4[nt][2] - mn1); ls1 += s4[nt][2];
            s4[nt][3] = __expf(s4[nt][3] - mn1); ls1 += s4[nt][3];
        }
        ls0 += __shfl_xor_sync(0xffffffffu, ls0, 1);
        ls0 += __shfl_xor_sync(0xffffffffu, ls0, 2);
        ls1 += __shfl_xor_sync(0xffffffffu, ls1, 1);
        ls1 += __shfl_xor_sync(0xffffffffu, ls1, 2);
        l0s = l0s * cr0 + ls0;  l1s = l1s * cr1 + ls1;
        m0s = mn0;  m1s = mn1;
#pragma unroll
        for (int nt = 0; nt < 8; nt++) {
            o[nt][0] *= cr0; o[nt][1] *= cr0;
            o[nt][2] *= cr1; o[nt][3] *= cr1;
        }

        // stage P (warp-private rows)
#pragma unroll
        for (int nt = 0; nt < 4; nt++) {
            int c0 = nt * 8 + 2 * lc;
            *(float2*)&sm[SMP + tr0l * PST + c0] =
                make_float2(tff(s4[nt][0]), tff(s4[nt][1]));
            *(float2*)&sm[SMP + tr1l * PST + c0] =
                make_float2(tff(s4[nt][2]), tff(s4[nt][3]));
        }
        __syncwarp();

        // O += P V  (m16 x n64 x k32)
#pragma unroll
        for (int ks = 0; ks < 4; ks++) {
            int kk = ks * 8;
            uint32_t a[4], bf[8][2];
            a[0] = __float_as_uint(sm[SMP + tr0l * PST + kk + lc]);
            a[1] = __float_as_uint(sm[SMP + tr1l * PST + kk + lc]);
            a[2] = __float_as_uint(sm[SMP + tr0l * PST + kk + lc + 4]);
            a[3] = __float_as_uint(sm[SMP + tr1l * PST + kk + lc + 4]);
#pragma unroll
            for (int nt = 0; nt < 8; nt++) {
                int nb = nt * 8 + lr;
                bf[nt][0] = __float_as_uint(Vs[(kk + lc)     * VST + nb]);
                bf[nt][1] = __float_as_uint(Vs[(kk + lc + 4) * VST + nb]);
            }
#pragma unroll
            for (int nt = 0; nt < 8; nt++) mma_tf32(o[nt], a, bf[nt]);
        }
    }

    float inv0 = 1.0f / l0s, inv1 = 1.0f / l1s;
    int tr0 = t0 + w * 16 + lr;
#pragma unroll
    for (int nt = 0; nt < 8; nt++) {
        int d = h * HD + nt * 8 + 2 * lc;
        *(float2*)&g_att[(tr0 * B_SZ + b) * EMB + d] =
            make_float2(o[nt][0] * inv0, o[nt][1] * inv0);
        *(float2*)&g_att[((tr0 + 8) * B_SZ + b) * EMB + d] =
            make_float2(o[nt][2] * inv1, o[nt][3] * inv1);
    }
}

// ---------------- launch ---------------------------------------------------
extern "C" void kernel_launch(void* const* d_in, const int* in_sizes, int n_in,
                              void* d_out, int out_size) {
    const float* query = (const float*)d_in[0];
    const float* key   = (const float*)d_in[1];
    const float* value = (const float*)d_in[2];
    const unsigned char* mask = (const unsigned char*)d_in[3];
    const float* Wq = (const float*)d_in[4];
    const float* bq = (const float*)d_in[5];
    const float* Wk = (const float*)d_in[6];
    const float* bk = (const float*)d_in[7];
    const float* Wv = (const float*)d_in[8];
    const float* bv = (const float*)d_in[9];
    const float* Wo = (const float*)d_in[10];
    const float* bo = (const float*)d_in[11];
    const float* rel_bias = (const float*)d_in[12];
    float* out = (float*)d_out;

    float *pq, *pk, *pv, *patt;
    cudaGetSymbolAddress((void**)&pq,   g_q);
    cudaGetSymbolAddress((void**)&pk,   g_k);
    cudaGetSymbolAddress((void**)&pv,   g_v);
    cudaGetSymbolAddress((void**)&patt, g_att);

    const int GEMM_SMEM = SGS * 3 * 4;      // 56832
    const int ATTN_SMEM = SMTOT * 4;        // 99840
    cudaFuncSetAttribute(sgemm_tf32_v2,
                         cudaFuncAttributeMaxDynamicSharedMemorySize, GEMM_SMEM);
    cudaFuncSetAttribute(attn_tf32_v2,
                         cudaFuncAttributeMaxDynamicSharedMemorySize, ATTN_SMEM);

    bias_lut_kernel<<<(NH * 4096 + 255) / 256, 256>>>(rel_bias);

    GArgs qkv;
    qkv.X[0] = query; qkv.W[0] = Wq; qkv.Bv[0] = bq; qkv.Y[0] = pq; qkv.scale[0] = 0.125f;
    qkv.X[1] = key;   qkv.W[1] = Wk; qkv.Bv[1] = bk; qkv.Y[1] = pk; qkv.scale[1] = 1.0f;
    qkv.X[2] = value; qkv.W[2] = Wv; qkv.Bv[2] = bv; qkv.Y[2] = pv; qkv.scale[2] = 1.0f;
    dim3 gq(EMB / 128, MROWS / 128, 3);     // (6, 32, 3)
    sgemm_tf32_v2<<<gq, 256, GEMM_SMEM>>>(qkv);

    dim3 ga(T_LEN / 128, B_SZ * NH);        // (16, 24)
    attn_tf32_v2<<<ga, 256, ATTN_SMEM>>>(mask);

    GArgs op;
    op.X[0] = patt; op.W[0] = Wo; op.Bv[0] = bo; op.Y[0] = out; op.scale[0] = 1.0f;
    op.X[1] = patt; op.W[1] = Wo; op.Bv[1] = bo; op.Y[1] = out; op.scale[1] = 1.0f;
    op.X[2] = patt; op.W[2] = Wo; op.Bv[2] = bo; op.Y[2] = out; op.scale[2] = 1.0f;
    dim3 go(EMB / 128, MROWS / 128, 1);
    sgemm_tf32_v2<<<go, 256, GEMM_SMEM>>>(op);
}